// round 6
// baseline (speedup 1.0000x reference)
#include <cuda_runtime.h>
#include <cuda_fp16.h>
#include <mma.h>
#include <math.h>

using namespace nvcuda;

#define NN 10000
#define UU 64
#define EE 160000
#define DD 66
#define BN 160000   // B*N
#define BD 1056     // B*D
#define CAP 96      // per-row edge capacity (lambda=16, P(>=96) ~ 1e-43)

// gates GEMM: M64 x N128 x K80(pad of 66). A layout: [hxh(64) | inputs(2) | pad]
#define LDA_G 88
#define LDB_G 136
#define LDO_G 132
#define KP_G 80
#define SA_G_BYTES (64 * LDA_G * 2)            // 11264
#define SOUT_G_BYTES (64 * LDO_G * 4)          // 33792 (aliases sB region)
#define SMEM_G (SA_G_BYTES + SOUT_G_BYTES + 128 * 4)   // 45568

// fused spmm+cand: A 16 x K144(pad of 132), B 144 x 64
#define LDA_F 152
#define LDB_F 72
#define LDO_F 68
#define KP_C 144

// ---------------- scratch (device globals: allocation-free rule; zero-initialized) ----
__device__ __align__(16) __half g_x0h[(size_t)NN * BD];   // (n,b,d) fp16: inputs ++ r*hx
__device__ __align__(16) __half g_hxh[(size_t)BN * UU];   // fp16 copy of hx
__device__ __align__(16) __half g_uh [(size_t)BN * UU];   // update gate fp16
__device__ __align__(16) __half g_wfch[KP_G * 128];       // W_fc fp16 REORDERED; rows 66..79 = 0
__device__ __align__(16) __half g_wgh [KP_C * 64];        // W_g fp16; rows 132..143 = 0
__device__ int    g_cnt[NN];                              // zero on entry (restored by k_spcand)
__device__ int    g_scol[NN * CAP];
__device__ float  g_sval[NN * CAP];

// packed fp32x2 FMA (Blackwell FFMA2; exact fp32 semantics)
union F2U { float2 f; unsigned long long u; };
__device__ __forceinline__ float2 ffma2(float2 a, float2 b, float2 c) {
    F2U A, B_, C, D_;
    A.f = a; B_.f = b; C.f = c;
    asm("fma.rn.f32x2 %0, %1, %2, %3;" : "=l"(D_.u) : "l"(A.u), "l"(B_.u), "l"(C.u));
    return D_.f;
}
__device__ __forceinline__ float fsigmoid(float z) { return 1.f / (1.f + __expf(-z)); }
__device__ __forceinline__ float ftanh(float x) {
    float y; asm("tanh.approx.f32 %0, %1;" : "=f"(y) : "f"(x)); return y;
}
__device__ __forceinline__ void cp_async16(void* sdst, const void* gsrc) {
    unsigned s = (unsigned)__cvta_generic_to_shared(sdst);
    asm volatile("cp.async.cg.shared.global [%0], [%1], 16;" :: "r"(s), "l"(gsrc));
}
__device__ __forceinline__ void cp_commit() { asm volatile("cp.async.commit_group;"); }
__device__ __forceinline__ void cp_wait0()  { asm volatile("cp.async.wait_group 0;" ::: "memory"); }

// ---------------- kernel 0: scatter + weight cvt (W_fc reordered) + hx->fp16 ----------
__global__ void k_prep(const int* __restrict__ rows, const int* __restrict__ cols,
                       const float* __restrict__ vals,
                       const float* __restrict__ Wfc, const float* __restrict__ Wg,
                       const float* __restrict__ hx) {
    int gid = blockIdx.x * blockDim.x + threadIdx.x;
    if (gid < 4224) {                   // W_fc: 66 rows x 64 float2; reorder rows
        int k = gid >> 6, c = gid & 63;
        int kp = (k >= 2) ? (k - 2) : (k + 64);
        float2 w = ((const float2*)Wfc)[gid];
        ((__half2*)g_wfch)[kp * 64 + c] = __floats2half2_rn(w.x, w.y);
    } else if (gid < 8448) {            // W_g: 132*64 floats = 4224 float2
        int i = gid - 4224;
        float2 w = ((const float2*)Wg)[i];
        ((__half2*)g_wgh)[i] = __floats2half2_rn(w.x, w.y);
    }
    // hx -> fp16 (5.12M float2, grid-stride)
    const float2* hx2 = (const float2*)hx;
    __half2* hh2 = (__half2*)g_hxh;
    for (size_t i = gid; i < (size_t)BN * UU / 2; i += (size_t)gridDim.x * blockDim.x) {
        float2 v = hx2[i];
        hh2[i] = __floats2half2_rn(v.x, v.y);
    }
    // edge scatter
    if (gid < EE) {
        int r = rows[gid];
        int slot = atomicAdd(&g_cnt[r], 1);
        if (slot < CAP) {
            g_scol[r * CAP + slot] = cols[gid];
            g_sval[r * CAP + slot] = vals[gid];
        }
    }
}

// ---------------- kernel 1: gates via HMMA; writes x0h (r*hx ++ inputs) and u --------
__global__ void __launch_bounds__(256) k_gates(const float* __restrict__ inputs,
                                               const float* __restrict__ bfc) {
    extern __shared__ char smraw[];
    __half* sA   = (__half*)smraw;                        // 64 x LDA_G (preserved)
    __half* sB   = (__half*)(smraw + SA_G_BYTES);         // KP_G x LDB_G
    float*  sOut = (float*)(smraw + SA_G_BYTES);          // 64 x LDO_G (aliases sB)
    float*  sBias = (float*)(smraw + SA_G_BYTES + SOUT_G_BYTES);   // 128

    int tid = threadIdx.x;
    int r0 = blockIdx.x * 64;

    // sB via cp.async from reordered g_wfch (80 rows x 16 chunks of 16B)
#pragma unroll
    for (int i = tid; i < KP_G * 16; i += 256) {
        int k = i >> 4, c = i & 15;
        cp_async16(sB + k * LDB_G + c * 8, g_wfch + k * 128 + c * 8);
    }
    // sA: hxh rows via cp.async (64 rows x 8 chunks of 16B)
#pragma unroll
    for (int i = tid; i < 64 * 8; i += 256) {
        int r = i >> 3, c = i & 7;
        cp_async16(sA + r * LDA_G + c * 8, g_hxh + (size_t)(r0 + r) * 64 + c * 8);
    }
    cp_commit();
    // inputs at halves 64..65; zero pad 66..79
    if (tid < 64) {
        float2 xin = ((const float2*)inputs)[r0 + tid];
        *(__half2*)(sA + tid * LDA_G + 64) = __floats2half2_rn(xin.x, xin.y);
        __half2 zz = __half2half2(__float2half(0.f));
#pragma unroll
        for (int k = 66; k < KP_G; k += 2) *(__half2*)(sA + tid * LDA_G + k) = zz;
    }
    if (tid < 128) sBias[tid] = bfc[tid];
    cp_wait0();
    __syncthreads();

    // 8 warps: warp (wm, wn): m-tile wm (0..3), n-tiles wn*4 .. wn*4+3
    int wid = tid >> 5;
    int wm = wid & 3, wn = wid >> 2;
    wmma::fragment<wmma::accumulator, 16, 16, 16, float> c[4];
#pragma unroll
    for (int j = 0; j < 4; ++j) wmma::fill_fragment(c[j], 0.f);
#pragma unroll
    for (int k = 0; k < KP_G / 16; ++k) {
        wmma::fragment<wmma::matrix_a, 16, 16, 16, __half, wmma::row_major> a;
        wmma::load_matrix_sync(a, sA + wm * 16 * LDA_G + k * 16, LDA_G);
#pragma unroll
        for (int j = 0; j < 4; ++j) {
            wmma::fragment<wmma::matrix_b, 16, 16, 16, __half, wmma::row_major> b;
            wmma::load_matrix_sync(b, sB + k * 16 * LDB_G + (wn * 4 + j) * 16, LDB_G);
            wmma::mma_sync(c[j], a, b, c[j]);
        }
    }
    __syncthreads();   // sOut aliases sB (sA preserved)
#pragma unroll
    for (int j = 0; j < 4; ++j)
        wmma::store_matrix_sync(sOut + wm * 16 * LDO_G + (wn * 4 + j) * 16, c[j],
                                LDO_G, wmma::mem_row_major);
    __syncthreads();

    // epilogue: sigmoid; q<16 -> r-gate -> x0h = r * hxh(from sA); q>=16 -> u (fp16)
    for (int i = tid; i < 2048; i += 256) {
        int r = i >> 5, q = i & 31;
        int col = q * 4;
        int row = r0 + r;
        float4 z = *(float4*)(sOut + r * LDO_G + col);
        z.x = fsigmoid(z.x + sBias[col + 0]);
        z.y = fsigmoid(z.y + sBias[col + 1]);
        z.z = fsigmoid(z.z + sBias[col + 2]);
        z.w = fsigmoid(z.w + sBias[col + 3]);
        if (q < 16) {
            uint2 hraw = *(uint2*)(sA + r * LDA_G + col);   // hxh cols col..col+3
            float2 ha = __half22float2(*(__half2*)&hraw.x);
            float2 hb = __half22float2(*(__half2*)&hraw.y);
            int n = row % NN, b = row / NN;
            size_t base = (size_t)n * BD + b * DD + 2 + col;
            *(__half2*)(g_x0h + base)     = __floats2half2_rn(z.x * ha.x, z.y * ha.y);
            *(__half2*)(g_x0h + base + 2) = __floats2half2_rn(z.z * hb.x, z.w * hb.y);
        } else {
            __half2 a = __floats2half2_rn(z.x, z.y);
            __half2 b2 = __floats2half2_rn(z.z, z.w);
            uint2 uv;
            uv.x = *(unsigned*)&a; uv.y = *(unsigned*)&b2;
            ((uint2*)g_uh)[(size_t)row * 16 + (q - 16)] = uv;
        }
    }
    // x0h[n, b, 0:2] = inputs (fp16, from sA)
    if (tid < 64) {
        int row = r0 + tid;
        int n = row % NN, b = row / NN;
        *(__half2*)(g_x0h + (size_t)n * BD + b * DD) = *(__half2*)(sA + tid * LDA_G + 64);
    }
}

// ---------------- kernel 2: FUSED SpMM + candidate GEMM + GRU combine ----------------
// block per node n; 288 threads (9 warps). Gather uses 264 threads; MMA uses warps 0-7.
__global__ void __launch_bounds__(288) k_spcand(const float* __restrict__ hx,
                                                const float* __restrict__ bg,
                                                float* __restrict__ out) {
    __shared__ int   s_col[CAP];
    __shared__ float s_val[CAP];
    __shared__ float sBias[64];
    __shared__ __align__(16) __half sB[KP_C * LDB_F];   // 144 x 72
    __shared__ __align__(16) __half sA[16 * LDA_F];     // 16 x 152 (b-major, k interleaved)
    __shared__ float sPart[2][16 * LDO_F];              // two k-half partials

    int n = blockIdx.x;
    int tid = threadIdx.x;
    int cnt = min(g_cnt[n], CAP);

    // sB via cp.async (144 rows x 8 chunks of 16B = 1152 over 288 threads)
#pragma unroll
    for (int i = tid; i < KP_C * 8; i += 288) {
        int k = i >> 3, c = i & 7;
        cp_async16(sB + k * LDB_F + c * 8, g_wgh + k * 64 + c * 8);
    }
    cp_commit();
    if (tid < 64) sBias[tid] = bg[tid];
    // zero sA pad halves 132..151 (16 rows x 5 uint2)
    if (tid < 80) {
        int r = tid / 5, c = tid - r * 5;
        *(uint2*)(sA + r * LDA_F + 132 + c * 4) = make_uint2(0u, 0u);
    }
    if (tid < cnt) { s_col[tid] = g_scol[n * CAP + tid]; s_val[tid] = g_sval[n * CAP + tid]; }
    __syncthreads();
    if (tid == 0) g_cnt[n] = 0;   // restore for next call

    // gather + interleave into sA
    if (tid < 264) {
        float2 acc0 = make_float2(0.f, 0.f), acc1 = make_float2(0.f, 0.f);
        const uint2* x0h8 = (const uint2*)g_x0h;
        for (int i = 0; i < cnt; ++i) {
            float v = s_val[i];
            int   c = s_col[i];
            uint2 raw = x0h8[(size_t)c * 264 + tid];
            float2 fa = __half22float2(*(__half2*)&raw.x);
            float2 fb = __half22float2(*(__half2*)&raw.y);
            float2 vp = make_float2(v, v);
            acc0 = ffma2(fa, vp, acc0);
            acc1 = ffma2(fb, vp, acc1);
        }
        uint2 own = x0h8[(size_t)n * 264 + tid];
        __half x0e[4];
        *(__half2*)&x0e[0] = *(__half2*)&own.x;
        *(__half2*)&x0e[2] = *(__half2*)&own.y;
        float x1e[4] = {acc0.x, acc0.y, acc1.x, acc1.y};
        int j0 = tid * 4;
#pragma unroll
        for (int e = 0; e < 4; ++e) {
            int j = j0 + e;
            int b = j / DD, d = j - b * DD;
            *(__half2*)(sA + b * LDA_F + 2 * d) =
                __halves2half2(x0e[e], __float2half_rn(x1e[e]));
        }
    }
    cp_wait0();
    __syncthreads();

    // MMA: warps 0..7: wn = w&3 (n-tile), kh = w>>2 (k-half: 0 -> steps 0..4, 1 -> 5..8)
    int wid = tid >> 5;
    if (wid < 8) {
        int wn = wid & 3, kh = wid >> 2;
        int kbeg = kh ? 5 : 0, kend = kh ? 9 : 5;
        wmma::fragment<wmma::accumulator, 16, 16, 16, float> c;
        wmma::fill_fragment(c, 0.f);
        for (int k = kbeg; k < kend; ++k) {
            wmma::fragment<wmma::matrix_a, 16, 16, 16, __half, wmma::row_major> a;
            wmma::fragment<wmma::matrix_b, 16, 16, 16, __half, wmma::row_major> b;
            wmma::load_matrix_sync(a, sA + k * 16, LDA_F);
            wmma::load_matrix_sync(b, sB + k * 16 * LDB_F + wn * 16, LDB_F);
            wmma::mma_sync(c, a, b, c);
        }
        wmma::store_matrix_sync(&sPart[kh][wn * 16], c, LDO_F, wmma::mem_row_major);
    }
    __syncthreads();

    // epilogue: sum partials, tanh, GRU combine. 256 threads x 1 float4.
    if (tid < 256) {
        int r = tid >> 4, q = tid & 15;   // r = batch b, q*4 = col
        int col = q * 4;
        float4 z;
        z.x = sPart[0][r * LDO_F + col + 0] + sPart[1][r * LDO_F + col + 0] + sBias[col + 0];
        z.y = sPart[0][r * LDO_F + col + 1] + sPart[1][r * LDO_F + col + 1] + sBias[col + 1];
        z.z = sPart[0][r * LDO_F + col + 2] + sPart[1][r * LDO_F + col + 2] + sBias[col + 2];
        z.w = sPart[0][r * LDO_F + col + 3] + sPart[1][r * LDO_F + col + 3] + sBias[col + 3];
        z.x = ftanh(z.x); z.y = ftanh(z.y); z.z = ftanh(z.z); z.w = ftanh(z.w);
        size_t o = ((size_t)r * NN + n) * 16 + q;   // float4 units
        uint2 uv = ((const uint2*)g_uh)[o];
        float2 ua = __half22float2(*(__half2*)&uv.x);
        float2 ub = __half22float2(*(__half2*)&uv.y);
        float4 h4 = ((const float4*)hx)[o];
        float4 res;
        res.x = ua.x * h4.x + (1.f - ua.x) * z.x;
        res.y = ua.y * h4.y + (1.f - ua.y) * z.y;
        res.z = ub.x * h4.z + (1.f - ub.x) * z.z;
        res.w = ub.y * h4.w + (1.f - ub.y) * z.w;
        ((float4*)out)[o] = res;
    }
}

// ---------------- launcher ----------------
extern "C" void kernel_launch(void* const* d_in, const int* in_sizes, int n_in,
                              void* d_out, int out_size) {
    (void)in_sizes; (void)n_in; (void)out_size;
    const float* inputs = (const float*)d_in[0];
    const float* hx     = (const float*)d_in[1];
    const int*   rows   = (const int*)d_in[2];
    const int*   cols   = (const int*)d_in[3];
    const float* vals   = (const float*)d_in[4];
    const float* Wfc    = (const float*)d_in[5];
    const float* bfc    = (const float*)d_in[6];
    const float* Wg     = (const float*)d_in[7];
    const float* bg     = (const float*)d_in[8];
    float* out = (float*)d_out;

    cudaFuncSetAttribute(k_gates, cudaFuncAttributeMaxDynamicSharedMemorySize, SMEM_G);

    k_prep<<<(EE + 255) / 256, 256>>>(rows, cols, vals, Wfc, Wg, hx);
    k_gates<<<BN / 64, 256, SMEM_G>>>(inputs, bfc);
    k_spcand<<<NN, 288>>>(hx, bg, out);
}